// round 11
// baseline (speedup 1.0000x reference)
#include <cuda_runtime.h>
#include <cuda_bf16.h>
#include <cstdint>
#include <cstddef>

typedef __nv_bfloat16 bf16;

// Problem constants
#define BB   2
#define LL   2048
#define MM   (BB*LL)     // 4096
#define DD   768
#define DH   1536
#define N3   (3*DH)      // 4608
#define KC   (DH+DD)     // 2304 (hs|h2 fused K width)
#define NLAY 8
#define VV   50257
#define NCH  16
#define CHL  (LL/NCH)    // 128

// ---------------------------------------------------------------------------
// Scratch
// ---------------------------------------------------------------------------
__device__ float g_x  [MM*DD];
__device__ float g_h1 [MM*DD];
__device__ float g_s  [MM*DD];
__device__ float g_dab[(size_t)MM*N3];
__device__ float g_b3 [NLAY*N3];
__device__ float g_bcd[NLAY*DD];
__device__ float g_cp [BB*NCH*DH];
__device__ float g_cs [BB*NCH*DH];

__device__ __align__(16) bf16 x_h [MM*DD], x_l [MM*DD];
__device__ __align__(16) bf16 cs_h[(size_t)MM*KC], cs_l[(size_t)MM*KC];
__device__ __align__(16) bf16 s_h [MM*DD], s_l [MM*DD];
__device__ __align__(16) bf16 gg_h[MM*DD], gg_l[MM*DD];
__device__ __align__(16) bf16 xn_h[MM*DD], xn_l[MM*DD];

__device__ __align__(16) bf16 w1_h  [NLAY*DD*DD],         w1_l  [NLAY*DD*DD];
__device__ __align__(16) bf16 wP_h  [(size_t)NLAY*N3*DD], wP_l  [(size_t)NLAY*N3*DD];
__device__ __align__(16) bf16 wcd_h [(size_t)NLAY*DD*KC], wcd_l [(size_t)NLAY*DD*KC];
__device__ __align__(16) bf16 w2_h  [NLAY*DD*DD],         w2_l  [NLAY*DD*DD];
__device__ __align__(16) bf16 wL_h  [NLAY*DD*DD],         wL_l  [NLAY*DD*DD];
__device__ __align__(16) bf16 we_h  [(size_t)VV*DD],      we_l  [(size_t)VV*DD];

__device__ __forceinline__ float siluf(float v) {
    return v * (1.0f / (1.0f + expf(-v)));
}

__device__ __forceinline__ void split2(float x0, float x1, uint32_t& hi, uint32_t& lo) {
    asm("cvt.rn.bf16x2.f32 %0, %1, %2;" : "=r"(hi) : "f"(x1), "f"(x0));
    float h0 = __uint_as_float(hi << 16);
    float h1 = __uint_as_float(hi & 0xffff0000u);
    asm("cvt.rn.bf16x2.f32 %0, %1, %2;" : "=r"(lo) : "f"(x1 - h1), "f"(x0 - h0));
}

// ---------------------------------------------------------------------------
// Prologue split kernels
// ---------------------------------------------------------------------------
__global__ void split_kernel(const float* __restrict__ in,
                             bf16* __restrict__ hi, bf16* __restrict__ lo, int n4) {
    int i = blockIdx.x * blockDim.x + threadIdx.x;
    if (i >= n4) return;
    float4 v = reinterpret_cast<const float4*>(in)[i];
    uint32_t h0, l0, h1, l1;
    split2(v.x, v.y, h0, l0);
    split2(v.z, v.w, h1, l1);
    reinterpret_cast<uint2*>(hi)[i] = make_uint2(h0, h1);
    reinterpret_cast<uint2*>(lo)[i] = make_uint2(l0, l1);
}

__global__ void splitP_kernel(const float* __restrict__ dw, const float* __restrict__ aw,
                              const float* __restrict__ bw,
                              bf16* __restrict__ hi, bf16* __restrict__ lo) {
    int i = blockIdx.x * blockDim.x + threadIdx.x;
    const int per = DH * DD / 4;
    if (i >= NLAY * 3 * per) return;
    int l = i / (3 * per);
    int r = i - l * 3 * per;
    int p = r / per;
    int o = r - p * per;
    const float* src = (p == 0) ? dw : (p == 1) ? aw : bw;
    float4 v = reinterpret_cast<const float4*>(src + (size_t)l * DH * DD)[o];
    uint32_t h0, l0, h1, l1;
    split2(v.x, v.y, h0, l0);
    split2(v.z, v.w, h1, l1);
    reinterpret_cast<uint2*>(hi)[i] = make_uint2(h0, h1);
    reinterpret_cast<uint2*>(lo)[i] = make_uint2(l0, l1);
}

__global__ void splitcd_kernel(const float* __restrict__ cw, const float* __restrict__ dw,
                               bf16* __restrict__ hi, bf16* __restrict__ lo) {
    int i = blockIdx.x * blockDim.x + threadIdx.x;
    if (i >= NLAY * DD * KC / 4) return;
    int e0 = i * 4;
    int l  = e0 / (DD * KC);
    int r  = e0 - l * DD * KC;
    int d  = r / KC;
    int k  = r - d * KC;
    float4 v;
    if (k < DH) v = *reinterpret_cast<const float4*>(cw + ((size_t)l * DD + d) * DH + k);
    else        v = *reinterpret_cast<const float4*>(dw + ((size_t)l * DD + d) * DD + (k - DH));
    uint32_t h0, l0, h1, l1;
    split2(v.x, v.y, h0, l0);
    split2(v.z, v.w, h1, l1);
    reinterpret_cast<uint2*>(hi)[i] = make_uint2(h0, h1);
    reinterpret_cast<uint2*>(lo)[i] = make_uint2(l0, l1);
}

__global__ void bias3_kernel(const float* __restrict__ db, const float* __restrict__ ab,
                             const float* __restrict__ bb, float* __restrict__ o) {
    int idx = blockIdx.x * blockDim.x + threadIdx.x;
    if (idx >= NLAY * N3) return;
    int l = idx / N3;
    int r = idx - l * N3;
    int p = r / DH;
    int c = r - p * DH;
    const float* s = (p == 0) ? db : (p == 1) ? ab : bb;
    o[idx] = s[l * DH + c];
}

__global__ void biascd_kernel(const float* __restrict__ cb, const float* __restrict__ db,
                              float* __restrict__ o) {
    int idx = blockIdx.x * blockDim.x + threadIdx.x;
    if (idx >= NLAY * DD) return;
    o[idx] = cb[idx] + db[idx];
}

__global__ void embed_kernel(const int* __restrict__ tokens,
                             const float* __restrict__ embed,
                             float* __restrict__ x,
                             bf16* __restrict__ xh, bf16* __restrict__ xl) {
    int idx = blockIdx.x * blockDim.x + threadIdx.x;
    const int C4 = DD / 4;
    if (idx >= MM * C4) return;
    int m = idx / C4;
    int c = idx - m * C4;
    int t = tokens[m];
    float4 v = reinterpret_cast<const float4*>(embed + (size_t)t * DD)[c];
    reinterpret_cast<float4*>(x)[idx] = v;
    uint32_t h0, l0, h1, l1;
    split2(v.x, v.y, h0, l0);
    split2(v.z, v.w, h1, l1);
    reinterpret_cast<uint2*>(xh)[idx] = make_uint2(h0, h1);
    reinterpret_cast<uint2*>(xl)[idx] = make_uint2(l0, l1);
}

// ---------------------------------------------------------------------------
// BF16x3 GEMM, templated tile width BN.
//   C[M,N] = A[M,K] * W[N,K]^T
//   EPI 0: C = acc + bias ; EPI 2: C = acc + S ; EPI 3: planes = S*silu(acc)
//   SPLIT: emit hi/lo planes of result.
// 128xBN tile, BK=32, 256 thr, cp.async 2-stage, ldmatrix frags.
// BN==64: full-stage fragment pipeline (24 LDSM burst -> 72 MMA stream).
// ---------------------------------------------------------------------------
#define RPITCH 80

__device__ __forceinline__ uint32_t cvta_s(const void* p) {
    uint32_t a;
    asm("{ .reg .u64 t; cvta.to.shared.u64 t, %1; cvt.u32.u64 %0, t; }" : "=r"(a) : "l"(p));
    return a;
}
__device__ __forceinline__ void cp16(uint32_t sdst, const void* gsrc) {
    asm volatile("cp.async.cg.shared.global [%0], [%1], 16;" :: "r"(sdst), "l"(gsrc));
}
__device__ __forceinline__ void ldsm4(uint32_t* r, uint32_t a) {
    asm volatile("ldmatrix.sync.aligned.m8n8.x4.shared.b16 {%0,%1,%2,%3}, [%4];"
                 : "=r"(r[0]), "=r"(r[1]), "=r"(r[2]), "=r"(r[3]) : "r"(a));
}
__device__ __forceinline__ void mma16(float* c, const uint32_t* a, const uint32_t* b) {
    asm volatile(
        "mma.sync.aligned.m16n8k16.row.col.f32.bf16.bf16.f32 "
        "{%0,%1,%2,%3}, {%4,%5,%6,%7}, {%8,%9}, {%0,%1,%2,%3};"
        : "+f"(c[0]), "+f"(c[1]), "+f"(c[2]), "+f"(c[3])
        : "r"(a[0]), "r"(a[1]), "r"(a[2]), "r"(a[3]), "r"(b[0]), "r"(b[1]));
}

template<int EPI, bool SPLIT, int BN>
__global__ __launch_bounds__(256, 2)
void gemm_bf3(const bf16* __restrict__ Ah, const bf16* __restrict__ Al,
              const bf16* __restrict__ Wh, const bf16* __restrict__ Wl,
              const float* __restrict__ bias, const float* __restrict__ S,
              float* __restrict__ C, bf16* __restrict__ Ch, bf16* __restrict__ Cl,
              int M, int N, int K, int lda) {
    extern __shared__ char smem[];
    const uint32_t sb = cvta_s(smem);

    constexpr int A_PLN = 128 * RPITCH;
    constexpr int B_PLN = BN * RPITCH;
    constexpr int STG   = 2 * A_PLN + 2 * B_PLN;
    constexpr int MT    = (BN == 128) ? 4 : 2;
    constexpr int NIT   = (1024 + BN * 8) / 256;

    const int tid  = threadIdx.x;
    const int warp = tid >> 5;
    const int lane = tid & 31;
    const int g    = lane >> 2;
    const int t4   = lane & 3;
    const int wm   = (BN == 128) ? (warp & 1) * 64 : (warp & 3) * 32;
    const int wn   = (BN == 128) ? (warp >> 1) * 32 : (warp >> 2) * 32;
    const int bm   = blockIdx.y * 128;
    const int bn   = blockIdx.x * BN;

    float acc[MT][4][4];
    #pragma unroll
    for (int mt = 0; mt < MT; mt++)
        #pragma unroll
        for (int nt = 0; nt < 4; nt++)
            #pragma unroll
            for (int r = 0; r < 4; r++)
                acc[mt][nt][r] = 0.0f;

    const int T = K / 32;
    const bf16* planes[4] = {Ah, Al, Wh, Wl};

    auto load_stage = [&](int stage, int k0) {
        #pragma unroll
        for (int i = 0; i < NIT; i++) {
            int idx = tid + i * 256;
            uint32_t d;
            const void* src;
            if (idx < 1024) {
                int p = idx >> 9, rem = idx & 511;
                int r = rem >> 2, c = rem & 3;
                d = sb + stage * STG + p * A_PLN + r * RPITCH + c * 16;
                src = planes[p] + (size_t)(bm + r) * lda + k0 + c * 8;
            } else {
                int j = idx - 1024;
                int p = j / (BN * 4), rem = j - p * (BN * 4);
                int r = rem >> 2, c = rem & 3;
                d = sb + stage * STG + 2 * A_PLN + p * B_PLN + r * RPITCH + c * 16;
                int n = bn + r;
                src = planes[2 + p] + (size_t)(n < N ? n : 0) * K + k0 + c * 8;
            }
            cp16(d, src);
        }
        asm volatile("cp.async.commit_group;" ::: "memory");
    };

    const int aoff = (lane & 15) * RPITCH + ((lane >> 4) & 1) * 16;
    const int boff = (((lane >> 4) & 1) * 8 + (lane & 7)) * RPITCH + ((lane >> 3) & 1) * 16;

    load_stage(0, 0);

    for (int tI = 0; tI < T; tI++) {
        const int s = tI & 1;
        if (tI + 1 < T) {
            load_stage(s ^ 1, (tI + 1) * 32);
            asm volatile("cp.async.wait_group 1;" ::: "memory");
        } else {
            asm volatile("cp.async.wait_group 0;" ::: "memory");
        }
        __syncthreads();

        const uint32_t stg = sb + s * STG;

        if (BN == 64) {
            // ---- full-stage fragment pipeline: 24 LDSM burst, then 72 MMA ----
            uint32_t ahi[2][2][4], alo[2][2][4], bhi[2][4][2], blo[2][4][2];
            #pragma unroll
            for (int kb = 0; kb < 2; kb++) {
                const uint32_t kboff = kb * 32;
                #pragma unroll
                for (int mt = 0; mt < 2; mt++)
                    ldsm4(alo[kb][mt], stg + A_PLN + (wm + mt * 16) * RPITCH + kboff + aoff);
                #pragma unroll
                for (int mt = 0; mt < 2; mt++)
                    ldsm4(ahi[kb][mt], stg + (wm + mt * 16) * RPITCH + kboff + aoff);
                #pragma unroll
                for (int q = 0; q < 2; q++) {
                    uint32_t tb[4];
                    ldsm4(tb, stg + 2 * A_PLN + (wn + q * 16) * RPITCH + kboff + boff);
                    bhi[kb][2 * q][0] = tb[0]; bhi[kb][2 * q][1] = tb[1];
                    bhi[kb][2 * q + 1][0] = tb[2]; bhi[kb][2 * q + 1][1] = tb[3];
                }
                #pragma unroll
                for (int q = 0; q < 2; q++) {
                    uint32_t tb[4];
                    ldsm4(tb, stg + 2 * A_PLN + B_PLN + (wn + q * 16) * RPITCH + kboff + boff);
                    blo[kb][2 * q][0] = tb[0]; blo[kb][2 * q][1] = tb[1];
                    blo[kb][2 * q + 1][0] = tb[2]; blo[kb][2 * q + 1][1] = tb[3];
                }
            }
            #pragma unroll
            for (int kb = 0; kb < 2; kb++) {
                #pragma unroll
                for (int mt = 0; mt < 2; mt++)
                    #pragma unroll
                    for (int nt = 0; nt < 4; nt++)
                        mma16(acc[mt][nt], alo[kb][mt], bhi[kb][nt]);
                #pragma unroll
                for (int mt = 0; mt < 2; mt++)
                    #pragma unroll
                    for (int nt = 0; nt < 4; nt++)
                        mma16(acc[mt][nt], ahi[kb][mt], blo[kb][nt]);
                #pragma unroll
                for (int mt = 0; mt < 2; mt++)
                    #pragma unroll
                    for (int nt = 0; nt < 4; nt++)
                        mma16(acc[mt][nt], ahi[kb][mt], bhi[kb][nt]);
            }
        } else {
            // ---- BN=128: per-kb interleave (register budget) ----
            #pragma unroll
            for (int kb = 0; kb < 2; kb++) {
                const uint32_t kboff = kb * 32;
                uint32_t bhi[4][2];
                #pragma unroll
                for (int q = 0; q < 2; q++) {
                    uint32_t tb[4];
                    ldsm4(tb, stg + 2 * A_PLN + (wn + q * 16) * RPITCH + kboff + boff);
                    bhi[2 * q][0] = tb[0]; bhi[2 * q][1] = tb[1];
                    bhi[2 * q + 1][0] = tb[2]; bhi[2 * q + 1][1] = tb[3];
                }
                {
                    uint32_t alo[MT][4];
                    #pragma unroll
                    for (int mt = 0; mt < MT; mt++)
                        ldsm4(alo[mt], stg + A_PLN + (wm + mt * 16) * RPITCH + kboff + aoff);
                    #pragma unroll
                    for (int mt = 0; mt < MT; mt++)
                        #pragma unroll
                        for (int nt = 0; nt < 4; nt++)
                            mma16(acc[mt][nt], alo[mt], bhi[nt]);
                }
                uint32_t ahi[MT][4];
                #pragma unroll
                for (int mt = 0; mt < MT; mt++)
                    ldsm4(ahi[mt], stg + (wm + mt * 16) * RPITCH + kboff + aoff);
                {
                    uint32_t blo[4][2];
                    #pragma unroll
                    for (int q = 0; q < 2; q++) {
                        uint32_t tb[4];
                        ldsm4(tb, stg + 2 * A_PLN + B_PLN + (wn + q * 16) * RPITCH + kboff + boff);
                        blo[2 * q][0] = tb[0]; blo[2 * q][1] = tb[1];
                        blo[2 * q + 1][0] = tb[2]; blo[2 * q + 1][1] = tb[3];
                    }
                    #pragma unroll
                    for (int mt = 0; mt < MT; mt++)
                        #pragma unroll
                        for (int nt = 0; nt < 4; nt++)
                            mma16(acc[mt][nt], ahi[mt], blo[nt]);
                }
                #pragma unroll
                for (int mt = 0; mt < MT; mt++)
                    #pragma unroll
                    for (int nt = 0; nt < 4; nt++)
                        mma16(acc[mt][nt], ahi[mt], bhi[nt]);
            }
        }
        __syncthreads();
    }

    // epilogue
    #pragma unroll
    for (int mt = 0; mt < MT; mt++) {
        #pragma unroll
        for (int i = 0; i < 2; i++) {
            int m = bm + wm + mt * 16 + g + i * 8;
            #pragma unroll
            for (int nt = 0; nt < 4; nt++) {
                int n0 = bn + wn + nt * 8 + t4 * 2;
                float vv[2];
                bool ok[2];
                #pragma unroll
                for (int j = 0; j < 2; j++) {
                    int n = n0 + j;
                    ok[j] = (n < N);
                    float v = acc[mt][nt][i * 2 + j];
                    size_t idx = (size_t)m * N + n;
                    if (ok[j]) {
                        if (bias) v += __ldg(&bias[n]);
                        if (EPI == 2) v += S[idx];
                        if (EPI == 3) v = S[idx] * siluf(v);
                        if (EPI != 3) C[idx] = v;
                    }
                    vv[j] = v;
                }
                if (SPLIT && ok[1]) {
                    size_t idx = (size_t)m * N + n0;
                    uint32_t h, l;
                    split2(vv[0], vv[1], h, l);
                    *reinterpret_cast<uint32_t*>(Ch + idx) = h;
                    *reinterpret_cast<uint32_t*>(Cl + idx) = l;
                }
            }
        }
    }
}

// ---------------------------------------------------------------------------
// conv1d (k=3, pad=1) + SiLU -> planes into csA[:, DH + e]
// ---------------------------------------------------------------------------
__global__ void conv_silu_kernel(const float* __restrict__ h,
                                 const float* __restrict__ cw,
                                 const float* __restrict__ cb,
                                 bf16* __restrict__ oh, bf16* __restrict__ ol) {
    int i = blockIdx.x * blockDim.x + threadIdx.x;
    if (i >= MM * DD / 2) return;
    const int D2 = DD / 2;
    int row = i / D2;
    int e   = (i - row * D2) * 2;
    int l   = row % LL;
    float2 cur  = reinterpret_cast<const float2*>(h)[i];
    float2 prev = (l > 0)      ? reinterpret_cast<const float2*>(h)[i - D2] : make_float2(0.f, 0.f);
    float2 next = (l < LL - 1) ? reinterpret_cast<const float2*>(h)[i + D2] : make_float2(0.f, 0.f);
    float v0 = prev.x * __ldg(&cw[e * 3 + 0]) + cur.x * __ldg(&cw[e * 3 + 1])
             + next.x * __ldg(&cw[e * 3 + 2]) + __ldg(&cb[e]);
    float v1 = prev.y * __ldg(&cw[e * 3 + 3]) + cur.y * __ldg(&cw[e * 3 + 4])
             + next.y * __ldg(&cw[e * 3 + 5]) + __ldg(&cb[e + 1]);
    v0 = siluf(v0);
    v1 = siluf(v1);
    uint32_t hh, ll2;
    split2(v0, v1, hh, ll2);
    size_t o = ((size_t)row * KC + DH + e) >> 1;
    reinterpret_cast<uint32_t*>(oh)[o] = hh;
    reinterpret_cast<uint32_t*>(ol)[o] = ll2;
}

// ---------------------------------------------------------------------------
// Chunked scan with on-the-fly A_bar
// ---------------------------------------------------------------------------
__device__ __forceinline__ float abar_of(float xdin, float a) {
    float xd = fmaxf(xdin, 0.0f) + log1pf(expf(-fabsf(xdin)));
    return expf(-xd * a);
}

__global__ void scan1_kernel(const float* __restrict__ dab,
                             float* __restrict__ cp, float* __restrict__ cs) {
    int gid = blockIdx.x * blockDim.x + threadIdx.x;
    if (gid >= BB * NCH * DH) return;
    int h  = gid % DH;
    int ch = (gid / DH) % NCH;
    int b  = gid / (DH * NCH);
    float p = 1.0f, s = 0.0f;
    for (int t = 0; t < CHL; t++) {
        size_t base = ((size_t)(b * LL + ch * CHL + t)) * N3;
        float a  = abar_of(dab[base + h], dab[base + DH + h]);
        float bx = dab[base + 2 * DH + h];
        p *= a;
        s = fmaf(bx, p, s);
    }
    cp[gid] = p;
    cs[gid] = s;
}

__global__ void scan2_kernel(float* __restrict__ cp, float* __restrict__ cs) {
    int gid = blockIdx.x * blockDim.x + threadIdx.x;
    if (gid >= BB * DH) return;
    int b = gid / DH;
    int h = gid - b * DH;
    float P = 1.0f, S = 0.0f;
    for (int ch = 0; ch < NCH; ch++) {
        size_t idx = ((size_t)b * NCH + ch) * DH + h;
        float p = cp[idx], s = cs[idx];
        cp[idx] = P;
        cs[idx] = S;
        S = fmaf(P, s, S);
        P *= p;
    }
}

__global__ void scan3_kernel(const float* __restrict__ dab,
                             const float* __restrict__ cp, const float* __restrict__ cs,
                             bf16* __restrict__ hh, bf16* __restrict__ hl) {
    int gid = blockIdx.x * blockDim.x + threadIdx.x;
    if (gid >= BB * NCH * DH) return;
    int h  = gid % DH;
    int ch = (gid / DH) % NCH;
    int b  = gid / (DH * NCH);
    float p = cp[gid];
    float s = cs[gid];
    for (int t = 0; t < CHL; t++) {
        size_t row  = (size_t)(b * LL + ch * CHL + t);
        size_t base = row * N3;
        float a  = abar_of(dab[base + h], dab[base + DH + h]);
        float bx = dab[base + 2 * DH + h];
        p *= a;
        s = fmaf(bx, p, s);
        size_t o = row * KC + h;
        bf16 hv = __float2bfloat16_rn(s);
        hh[o] = hv;
        hl[o] = __float2bfloat16_rn(s - __bfloat162float(hv));
    }
}

// ---------------------------------------------------------------------------
// LayerNorm -> xn planes
// ---------------------------------------------------------------------------
__global__ __launch_bounds__(256)
void ln_kernel(const float* __restrict__ x, const float* __restrict__ gw,
               const float* __restrict__ bw, bf16* __restrict__ yh,
               bf16* __restrict__ yl) {
    int row = blockIdx.x;
    const float* xr = x + (size_t)row * DD;
    int tid = threadIdx.x;

    __shared__ float red[8];
    __shared__ float stat[2];

    float v[3];
    float sum = 0.0f;
    #pragma unroll
    for (int i = 0; i < 3; i++) { v[i] = xr[tid + i * 256]; sum += v[i]; }
    #pragma unroll
    for (int o = 16; o > 0; o >>= 1) sum += __shfl_xor_sync(0xffffffffu, sum, o);
    if ((tid & 31) == 0) red[tid >> 5] = sum;
    __syncthreads();
    if (tid == 0) {
        float t = 0.0f;
        #pragma unroll
        for (int w = 0; w < 8; w++) t += red[w];
        stat[0] = t;
    }
    __syncthreads();
    float mu = stat[0] * (1.0f / (float)DD);

    float vs = 0.0f;
    #pragma unroll
    for (int i = 0; i < 3; i++) { float d = v[i] - mu; vs += d * d; }
    #pragma unroll
    for (int o = 16; o > 0; o >>= 1) vs += __shfl_xor_sync(0xffffffffu, vs, o);
    if ((tid & 31) == 0) red[tid >> 5] = vs;
    __syncthreads();
    if (tid == 0) {
        float t = 0.0f;
        #pragma unroll
        for (int w = 0; w < 8; w++) t += red[w];
        stat[1] = t;
    }
    __syncthreads();
    float rstd = rsqrtf(stat[1] * (1.0f / (float)DD) + 1e-5f);

    #pragma unroll
    for (int i = 0; i < 3; i++) {
        int e = tid + i * 256;
        float r = (v[i] - mu) * rstd * __ldg(&gw[e]) + __ldg(&bw[e]);
        size_t idx = (size_t)row * DD + e;
        bf16 hv = __float2bfloat16_rn(r);
        yh[idx] = hv;
        yl[idx] = __float2bfloat16_rn(r - __bfloat162float(hv));
    }
}

// ---------------------------------------------------------------------------
// Launcher
// ---------------------------------------------------------------------------
extern "C" void kernel_launch(void* const* d_in, const int* in_sizes, int n_in,
                              void* d_out, int out_size) {
    const int*   tokens  = (const int*)  d_in[0];
    const float* embed   = (const float*)d_in[1];
    const float* lin1_w  = (const float*)d_in[2];
    const float* conv_w  = (const float*)d_in[3];
    const float* conv_b  = (const float*)d_in[4];
    const float* A_w     = (const float*)d_in[5];
    const float* A_b     = (const float*)d_in[6];
    const float* B_w     = (const float*)d_in[7];
    const float* B_b     = (const float*)d_in[8];
    const float* del_w   = (const float*)d_in[9];
    const float* del_b   = (const float*)d_in[10];
    const float* C_w     = (const float*)d_in[11];
    const float* C_b     = (const float*)d_in[12];
    const float* D_w     = (const float*)d_in[13];
    const float* D_b     = (const float*)d_in[14];
    const float* lin2_w  = (const float*)d_in[15];
    const float* last_w  = (const float*)d_in[16];
    const float* ln_g    = (const float*)d_in[17];
    const float* ln_b    = (const float*)d_in[18];
    float* out = (float*)d_out;

    float *x, *h1, *s, *dab, *b3, *bcd, *cp, *cs;
    cudaGetSymbolAddress((void**)&x,   g_x);
    cudaGetSymbolAddress((void**)&h1,  g_h1);
    cudaGetSymbolAddress((void**)&s,   g_s);
    cudaGetSymbolAddress((void**)&dab, g_dab);
    cudaGetSymbolAddress((void**)&b3,  g_b3);
    cudaGetSymbolAddress((void**)&bcd, g_bcd);
    cudaGetSymbolAddress((void**)&cp,  g_cp);
    cudaGetSymbolAddress((void**)&cs,  g_cs);

    bf16 *xh, *xl, *csh, *csl, *sh, *sl, *ggh, *ggl, *xnh, *xnl;
    cudaGetSymbolAddress((void**)&xh,  x_h);  cudaGetSymbolAddress((void**)&xl,  x_l);
    cudaGetSymbolAddress((void**)&csh, cs_h); cudaGetSymbolAddress((void**)&csl, cs_l);
    cudaGetSymbolAddress((void**)&sh,  s_h);  cudaGetSymbolAddress((void**)&sl,  s_l);
    cudaGetSymbolAddress((void**)&ggh, gg_h); cudaGetSymbolAddress((void**)&ggl, gg_l);
    cudaGetSymbolAddress((void**)&xnh, xn_h); cudaGetSymbolAddress((void**)&xnl, xn_l);

    bf16 *p1h, *p1l, *pPh, *pPl, *pcdh, *pcdl, *p2h, *p2l, *pLh, *pLl, *peh, *pel;
    cudaGetSymbolAddress((void**)&p1h, w1_h);   cudaGetSymbolAddress((void**)&p1l, w1_l);
    cudaGetSymbolAddress((void**)&pPh, wP_h);   cudaGetSymbolAddress((void**)&pPl, wP_l);
    cudaGetSymbolAddress((void**)&pcdh, wcd_h); cudaGetSymbolAddress((void**)&pcdl, wcd_l);
    cudaGetSymbolAddress((void**)&p2h, w2_h);   cudaGetSymbolAddress((void**)&p2l, w2_l);
    cudaGetSymbolAddress((void**)&pLh, wL_h);   cudaGetSymbolAddress((void**)&pLl, wL_l);
    cudaGetSymbolAddress((void**)&peh, we_h);   cudaGetSymbolAddress((void**)&pel, we_l);

    const int GS64  = 2 * (2 * 128 * RPITCH + 2 * 64 * RPITCH);    // 61440
    const int GS128 = 2 * (2 * 128 * RPITCH + 2 * 128 * RPITCH);   // 81920
    cudaFuncSetAttribute((void*)gemm_bf3<0,false,128>, cudaFuncAttributeMaxDynamicSharedMemorySize, GS128);
    cudaFuncSetAttribute((void*)gemm_bf3<0,false,64>,  cudaFuncAttributeMaxDynamicSharedMemorySize, GS64);
    cudaFuncSetAttribute((void*)gemm_bf3<0,true ,64>,  cudaFuncAttributeMaxDynamicSharedMemorySize, GS64);
    cudaFuncSetAttribute((void*)gemm_bf3<2,true ,64>,  cudaFuncAttributeMaxDynamicSharedMemorySize, GS64);
    cudaFuncSetAttribute((void*)gemm_bf3<3,true ,64>,  cudaFuncAttributeMaxDynamicSharedMemorySize, GS64);

    const dim3 blk(256);
    const dim3 gd768(DD / 64, MM / 128);             // 12 x 32 (BN=64)
    const dim3 gdP(N3 / 128, MM / 128);              // 36 x 32 (BN=128)
    const dim3 gdV((VV + 127) / 128, MM / 128);      // 393 x 32 (BN=128)

    const int ndd = NLAY * DD * DD / 4, nem = VV * DD / 4;
    const int npP = NLAY * 3 * DH * DD / 4, npcd = NLAY * DD * KC / 4;

    // Launch order keeps layer-0 lin1 GEMM at my launch #4 (the profiled slot).
    split_kernel<<<(ndd + 255) / 256, 256>>>(lin1_w, p1h, p1l, ndd);                 // 1
    embed_kernel<<<(MM * (DD / 4) + 255) / 256, 256>>>(tokens, embed, x, xh, xl);    // 2
    bias3_kernel<<<(NLAY * N3 + 255) / 256, 256>>>(del_b, A_b, B_b, b3);             // 3

    for (int i = 0; i < NLAY; i++) {
        size_t odd = (size_t)i * DD * DD;
        size_t opr = (size_t)i * 3 * DH * DD;
        size_t ocd = (size_t)i * DD * KC;
        const float* cw  = conv_w + (size_t)i * DD * 3;
        const float* cb  = conv_b + (size_t)i * DD;

        // h1 = x @ lin1^T  (layer 0: launch #4 -> profiled)
        gemm_bf3<0,false,64><<<gd768, blk, GS64>>>(xh, xl, p1h + odd, p1l + odd,
            nullptr, nullptr, h1, nullptr, nullptr, MM, DD, DD, DD);

        if (i == 0) {   // remaining prologue, after the profiled GEMM
            biascd_kernel<<<(NLAY * DD + 255) / 256, 256>>>(C_b, D_b, bcd);
            splitP_kernel<<<(npP + 255) / 256, 256>>>(del_w, A_w, B_w, pPh, pPl);
            splitcd_kernel<<<(npcd + 255) / 256, 256>>>(C_w, D_w, pcdh, pcdl);
            split_kernel<<<(ndd + 255) / 256, 256>>>(lin2_w, p2h, p2l, ndd);
            split_kernel<<<(ndd + 255) / 256, 256>>>(last_w, pLh, pLl, ndd);
            split_kernel<<<(nem + 255) / 256, 256>>>(embed,  peh, pel, nem);
        }

        // h2 planes = silu(conv1d(h1)) -> csA[:, DH:]
        conv_silu_kernel<<<(MM * DD / 2 + 255) / 256, 256>>>(h1, cw, cb, csh, csl);
        // fused delta|A|B projection
        gemm_bf3<0,false,128><<<gdP, blk, GS128>>>(csh + DH, csl + DH, pPh + opr, pPl + opr,
            b3 + (size_t)i * N3, nullptr, dab, nullptr, nullptr, MM, N3, DD, KC);
        // chunked scan -> hs planes into csA[:, :DH]
        scan1_kernel<<<(BB * NCH * DH + 255) / 256, 256>>>(dab, cp, cs);
        scan2_kernel<<<(BB * DH + 255) / 256, 256>>>(cp, cs);
        scan3_kernel<<<(BB * NCH * DH + 255) / 256, 256>>>(dab, cp, cs, csh, csl);
        // s = [hs|h2] @ [Cw|Dw]^T + (Cb+Db)
        gemm_bf3<0,true,64><<<gd768, blk, GS64>>>(csh, csl, pcdh + ocd, pcdl + ocd,
            bcd + (size_t)i * DD, nullptr, s, sh, sl, MM, DD, KC, KC);
        // gate = s * silu(s @ lin2^T)
        gemm_bf3<3,true,64><<<gd768, blk, GS64>>>(sh, sl, p2h + odd, p2l + odd,
            nullptr, s, nullptr, ggh, ggl, MM, DD, DD, DD);
        // x = s + gate @ last^T
        gemm_bf3<2,true,64><<<gd768, blk, GS64>>>(ggh, ggl, pLh + odd, pLl + odd,
            nullptr, s, x, xh, xl, MM, DD, DD, DD);
    }

    ln_kernel<<<MM, 256>>>(x, ln_g, ln_b, xnh, xnl);
    gemm_bf3<0,false,128><<<gdV, blk, GS128>>>(xnh, xnl, peh, pel,
        nullptr, nullptr, out, nullptr, nullptr, MM, VV, DD, DD);
}

// round 12
// speedup vs baseline: 1.0041x; 1.0041x over previous
#include <cuda_runtime.h>
#include <cuda_bf16.h>
#include <cstdint>
#include <cstddef>

typedef __nv_bfloat16 bf16;

// Problem constants
#define BB   2
#define LL   2048
#define MM   (BB*LL)     // 4096
#define DD   768
#define DH   1536
#define N3   (3*DH)      // 4608
#define KC   (DH+DD)     // 2304 (hs|h2 fused K width)
#define NLAY 8
#define VV   50257
#define NCH  16
#define CHL  (LL/NCH)    // 128

// ---------------------------------------------------------------------------
// Scratch
// ---------------------------------------------------------------------------
__device__ float g_x  [MM*DD];
__device__ float g_h1 [MM*DD];
__device__ float g_s  [MM*DD];
__device__ float g_dab[(size_t)MM*N3];
__device__ float g_b3 [NLAY*N3];
__device__ float g_bcd[NLAY*DD];
__device__ float g_cp [BB*NCH*DH];
__device__ float g_cs [BB*NCH*DH];

__device__ __align__(16) bf16 x_h [MM*DD], x_l [MM*DD];
__device__ __align__(16) bf16 cs_h[(size_t)MM*KC], cs_l[(size_t)MM*KC];
__device__ __align__(16) bf16 s_h [MM*DD], s_l [MM*DD];
__device__ __align__(16) bf16 gg_h[MM*DD], gg_l[MM*DD];
__device__ __align__(16) bf16 xn_h[MM*DD], xn_l[MM*DD];

__device__ __align__(16) bf16 w1_h  [NLAY*DD*DD],         w1_l  [NLAY*DD*DD];
__device__ __align__(16) bf16 wP_h  [(size_t)NLAY*N3*DD], wP_l  [(size_t)NLAY*N3*DD];
__device__ __align__(16) bf16 wcd_h [(size_t)NLAY*DD*KC], wcd_l [(size_t)NLAY*DD*KC];
__device__ __align__(16) bf16 w2_h  [NLAY*DD*DD],         w2_l  [NLAY*DD*DD];
__device__ __align__(16) bf16 wL_h  [NLAY*DD*DD],         wL_l  [NLAY*DD*DD];
__device__ __align__(16) bf16 we_h  [(size_t)VV*DD],      we_l  [(size_t)VV*DD];

__device__ __forceinline__ float siluf(float v) {
    return v * (1.0f / (1.0f + expf(-v)));
}

__device__ __forceinline__ void split2(float x0, float x1, uint32_t& hi, uint32_t& lo) {
    asm("cvt.rn.bf16x2.f32 %0, %1, %2;" : "=r"(hi) : "f"(x1), "f"(x0));
    float h0 = __uint_as_float(hi << 16);
    float h1 = __uint_as_float(hi & 0xffff0000u);
    asm("cvt.rn.bf16x2.f32 %0, %1, %2;" : "=r"(lo) : "f"(x1 - h1), "f"(x0 - h0));
}

// ---------------------------------------------------------------------------
// Prologue split kernels
// ---------------------------------------------------------------------------
__global__ void split_kernel(const float* __restrict__ in,
                             bf16* __restrict__ hi, bf16* __restrict__ lo, int n4) {
    int i = blockIdx.x * blockDim.x + threadIdx.x;
    if (i >= n4) return;
    float4 v = reinterpret_cast<const float4*>(in)[i];
    uint32_t h0, l0, h1, l1;
    split2(v.x, v.y, h0, l0);
    split2(v.z, v.w, h1, l1);
    reinterpret_cast<uint2*>(hi)[i] = make_uint2(h0, h1);
    reinterpret_cast<uint2*>(lo)[i] = make_uint2(l0, l1);
}

__global__ void splitP_kernel(const float* __restrict__ dw, const float* __restrict__ aw,
                              const float* __restrict__ bw,
                              bf16* __restrict__ hi, bf16* __restrict__ lo) {
    int i = blockIdx.x * blockDim.x + threadIdx.x;
    const int per = DH * DD / 4;
    if (i >= NLAY * 3 * per) return;
    int l = i / (3 * per);
    int r = i - l * 3 * per;
    int p = r / per;
    int o = r - p * per;
    const float* src = (p == 0) ? dw : (p == 1) ? aw : bw;
    float4 v = reinterpret_cast<const float4*>(src + (size_t)l * DH * DD)[o];
    uint32_t h0, l0, h1, l1;
    split2(v.x, v.y, h0, l0);
    split2(v.z, v.w, h1, l1);
    reinterpret_cast<uint2*>(hi)[i] = make_uint2(h0, h1);
    reinterpret_cast<uint2*>(lo)[i] = make_uint2(l0, l1);
}

__global__ void splitcd_kernel(const float* __restrict__ cw, const float* __restrict__ dw,
                               bf16* __restrict__ hi, bf16* __restrict__ lo) {
    int i = blockIdx.x * blockDim.x + threadIdx.x;
    if (i >= NLAY * DD * KC / 4) return;
    int e0 = i * 4;
    int l  = e0 / (DD * KC);
    int r  = e0 - l * DD * KC;
    int d  = r / KC;
    int k  = r - d * KC;
    float4 v;
    if (k < DH) v = *reinterpret_cast<const float4*>(cw + ((size_t)l * DD + d) * DH + k);
    else        v = *reinterpret_cast<const float4*>(dw + ((size_t)l * DD + d) * DD + (k - DH));
    uint32_t h0, l0, h1, l1;
    split2(v.x, v.y, h0, l0);
    split2(v.z, v.w, h1, l1);
    reinterpret_cast<uint2*>(hi)[i] = make_uint2(h0, h1);
    reinterpret_cast<uint2*>(lo)[i] = make_uint2(l0, l1);
}

__global__ void bias3_kernel(const float* __restrict__ db, const float* __restrict__ ab,
                             const float* __restrict__ bb, float* __restrict__ o) {
    int idx = blockIdx.x * blockDim.x + threadIdx.x;
    if (idx >= NLAY * N3) return;
    int l = idx / N3;
    int r = idx - l * N3;
    int p = r / DH;
    int c = r - p * DH;
    const float* s = (p == 0) ? db : (p == 1) ? ab : bb;
    o[idx] = s[l * DH + c];
}

__global__ void biascd_kernel(const float* __restrict__ cb, const float* __restrict__ db,
                              float* __restrict__ o) {
    int idx = blockIdx.x * blockDim.x + threadIdx.x;
    if (idx >= NLAY * DD) return;
    o[idx] = cb[idx] + db[idx];
}

__global__ void embed_kernel(const int* __restrict__ tokens,
                             const float* __restrict__ embed,
                             float* __restrict__ x,
                             bf16* __restrict__ xh, bf16* __restrict__ xl) {
    int idx = blockIdx.x * blockDim.x + threadIdx.x;
    const int C4 = DD / 4;
    if (idx >= MM * C4) return;
    int m = idx / C4;
    int c = idx - m * C4;
    int t = tokens[m];
    float4 v = reinterpret_cast<const float4*>(embed + (size_t)t * DD)[c];
    reinterpret_cast<float4*>(x)[idx] = v;
    uint32_t h0, l0, h1, l1;
    split2(v.x, v.y, h0, l0);
    split2(v.z, v.w, h1, l1);
    reinterpret_cast<uint2*>(xh)[idx] = make_uint2(h0, h1);
    reinterpret_cast<uint2*>(xl)[idx] = make_uint2(l0, l1);
}

// ---------------------------------------------------------------------------
// BF16x3 GEMM, templated SHAPE:
//   SHAPE 0: BM=128, BN=128, 256 thr (8 warps 2x4), 2 CTA/SM   (proj, head)
//   SHAPE 1: BM=64,  BN=64,  128 thr (4 warps 2x2), 5 CTA/SM   (lin1/cd/lin2/last)
//   C[M,N] = A[M,K] * W[N,K]^T
//   EPI 0: C = acc + bias ; EPI 2: C = acc + S ; EPI 3: planes = S*silu(acc)
//   SPLIT: emit hi/lo planes of result.
// BK=32, cp.async 2-stage, ldmatrix frags.
// ---------------------------------------------------------------------------
#define RPITCH 80

__device__ __forceinline__ uint32_t cvta_s(const void* p) {
    uint32_t a;
    asm("{ .reg .u64 t; cvta.to.shared.u64 t, %1; cvt.u32.u64 %0, t; }" : "=r"(a) : "l"(p));
    return a;
}
__device__ __forceinline__ void cp16(uint32_t sdst, const void* gsrc) {
    asm volatile("cp.async.cg.shared.global [%0], [%1], 16;" :: "r"(sdst), "l"(gsrc));
}
__device__ __forceinline__ void ldsm4(uint32_t* r, uint32_t a) {
    asm volatile("ldmatrix.sync.aligned.m8n8.x4.shared.b16 {%0,%1,%2,%3}, [%4];"
                 : "=r"(r[0]), "=r"(r[1]), "=r"(r[2]), "=r"(r[3]) : "r"(a));
}
__device__ __forceinline__ void mma16(float* c, const uint32_t* a, const uint32_t* b) {
    asm volatile(
        "mma.sync.aligned.m16n8k16.row.col.f32.bf16.bf16.f32 "
        "{%0,%1,%2,%3}, {%4,%5,%6,%7}, {%8,%9}, {%0,%1,%2,%3};"
        : "+f"(c[0]), "+f"(c[1]), "+f"(c[2]), "+f"(c[3])
        : "r"(a[0]), "r"(a[1]), "r"(a[2]), "r"(a[3]), "r"(b[0]), "r"(b[1]));
}

template<int EPI, bool SPLIT, int SHAPE>
__global__ __launch_bounds__((SHAPE ? 128 : 256), (SHAPE ? 5 : 2))
void gemm_bf3(const bf16* __restrict__ Ah, const bf16* __restrict__ Al,
              const bf16* __restrict__ Wh, const bf16* __restrict__ Wl,
              const float* __restrict__ bias, const float* __restrict__ S,
              float* __restrict__ C, bf16* __restrict__ Ch, bf16* __restrict__ Cl,
              int M, int N, int K, int lda) {
    extern __shared__ char smem[];
    const uint32_t sb = cvta_s(smem);

    constexpr int BMv   = SHAPE ? 64 : 128;
    constexpr int BNv   = SHAPE ? 64 : 128;
    constexpr int THR   = SHAPE ? 128 : 256;
    constexpr int A_PLN = BMv * RPITCH;
    constexpr int B_PLN = BNv * RPITCH;
    constexpr int STG   = 2 * A_PLN + 2 * B_PLN;
    constexpr int MT    = SHAPE ? 2 : 4;
    constexpr int ACH   = BMv * 8;                 // A-plane chunks per stage
    constexpr int NIT   = (BMv * 8 + BNv * 8) / THR;   // 8 for both shapes

    const int tid  = threadIdx.x;
    const int warp = tid >> 5;
    const int lane = tid & 31;
    const int g    = lane >> 2;
    const int t4   = lane & 3;
    const int wm   = SHAPE ? (warp & 1) * 32 : (warp & 1) * 64;
    const int wn   = SHAPE ? (warp >> 1) * 32 : (warp >> 1) * 32;
    const int bm   = blockIdx.y * BMv;
    const int bn   = blockIdx.x * BNv;

    float acc[MT][4][4];
    #pragma unroll
    for (int mt = 0; mt < MT; mt++)
        #pragma unroll
        for (int nt = 0; nt < 4; nt++)
            #pragma unroll
            for (int r = 0; r < 4; r++)
                acc[mt][nt][r] = 0.0f;

    const int T = K / 32;
    const bf16* planes[4] = {Ah, Al, Wh, Wl};

    auto load_stage = [&](int stage, int k0) {
        #pragma unroll
        for (int i = 0; i < NIT; i++) {
            int idx = tid + i * THR;
            uint32_t d;
            const void* src;
            if (idx < ACH) {
                int p = idx / (BMv * 4), rem = idx % (BMv * 4);
                int r = rem >> 2, c = rem & 3;
                d = sb + stage * STG + p * A_PLN + r * RPITCH + c * 16;
                src = planes[p] + (size_t)(bm + r) * lda + k0 + c * 8;
            } else {
                int j = idx - ACH;
                int p = j / (BNv * 4), rem = j % (BNv * 4);
                int r = rem >> 2, c = rem & 3;
                d = sb + stage * STG + 2 * A_PLN + p * B_PLN + r * RPITCH + c * 16;
                int n = bn + r;
                src = planes[2 + p] + (size_t)(n < N ? n : 0) * K + k0 + c * 8;
            }
            cp16(d, src);
        }
        asm volatile("cp.async.commit_group;" ::: "memory");
    };

    const int aoff = (lane & 15) * RPITCH + ((lane >> 4) & 1) * 16;
    const int boff = (((lane >> 4) & 1) * 8 + (lane & 7)) * RPITCH + ((lane >> 3) & 1) * 16;

    load_stage(0, 0);

    for (int tI = 0; tI < T; tI++) {
        const int s = tI & 1;
        if (tI + 1 < T) {
            load_stage(s ^ 1, (tI + 1) * 32);
            asm volatile("cp.async.wait_group 1;" ::: "memory");
        } else {
            asm volatile("cp.async.wait_group 0;" ::: "memory");
        }
        __syncthreads();

        const uint32_t stg = sb + s * STG;
        #pragma unroll
        for (int kb = 0; kb < 2; kb++) {
            const uint32_t kboff = kb * 32;
            uint32_t bhi[4][2];
            #pragma unroll
            for (int q = 0; q < 2; q++) {
                uint32_t tb[4];
                ldsm4(tb, stg + 2 * A_PLN + (wn + q * 16) * RPITCH + kboff + boff);
                bhi[2 * q][0] = tb[0]; bhi[2 * q][1] = tb[1];
                bhi[2 * q + 1][0] = tb[2]; bhi[2 * q + 1][1] = tb[3];
            }
            {   // Al * Wh
                uint32_t alo[MT][4];
                #pragma unroll
                for (int mt = 0; mt < MT; mt++)
                    ldsm4(alo[mt], stg + A_PLN + (wm + mt * 16) * RPITCH + kboff + aoff);
                #pragma unroll
                for (int mt = 0; mt < MT; mt++)
                    #pragma unroll
                    for (int nt = 0; nt < 4; nt++)
                        mma16(acc[mt][nt], alo[mt], bhi[nt]);
            }
            uint32_t ahi[MT][4];
            #pragma unroll
            for (int mt = 0; mt < MT; mt++)
                ldsm4(ahi[mt], stg + (wm + mt * 16) * RPITCH + kboff + aoff);
            {   // Ah * Wl
                uint32_t blo[4][2];
                #pragma unroll
                for (int q = 0; q < 2; q++) {
                    uint32_t tb[4];
                    ldsm4(tb, stg + 2 * A_PLN + B_PLN + (wn + q * 16) * RPITCH + kboff + boff);
                    blo[2 * q][0] = tb[0]; blo[2 * q][1] = tb[1];
                    blo[2 * q + 1][0] = tb[2]; blo[2 * q + 1][1] = tb[3];
                }
                #pragma unroll
                for (int mt = 0; mt < MT; mt++)
                    #pragma unroll
                    for (int nt = 0; nt < 4; nt++)
                        mma16(acc[mt][nt], ahi[mt], blo[nt]);
            }
            // Ah * Wh
            #pragma unroll
            for (int mt = 0; mt < MT; mt++)
                #pragma unroll
                for (int nt = 0; nt < 4; nt++)
                    mma16(acc[mt][nt], ahi[mt], bhi[nt]);
        }
        __syncthreads();
    }

    // epilogue
    #pragma unroll
    for (int mt = 0; mt < MT; mt++) {
        #pragma unroll
        for (int i = 0; i < 2; i++) {
            int m = bm + wm + mt * 16 + g + i * 8;
            #pragma unroll
            for (int nt = 0; nt < 4; nt++) {
                int n0 = bn + wn + nt * 8 + t4 * 2;
                float vv[2];
                bool ok[2];
                #pragma unroll
                for (int j = 0; j < 2; j++) {
                    int n = n0 + j;
                    ok[j] = (n < N);
                    float v = acc[mt][nt][i * 2 + j];
                    size_t idx = (size_t)m * N + n;
                    if (ok[j]) {
                        if (bias) v += __ldg(&bias[n]);
                        if (EPI == 2) v += S[idx];
                        if (EPI == 3) v = S[idx] * siluf(v);
                        if (EPI != 3) C[idx] = v;
                    }
                    vv[j] = v;
                }
                if (SPLIT && ok[1]) {
                    size_t idx = (size_t)m * N + n0;
                    uint32_t h, l;
                    split2(vv[0], vv[1], h, l);
                    *reinterpret_cast<uint32_t*>(Ch + idx) = h;
                    *reinterpret_cast<uint32_t*>(Cl + idx) = l;
                }
            }
        }
    }
}

// ---------------------------------------------------------------------------
// conv1d (k=3, pad=1) + SiLU -> planes into csA[:, DH + e]
// ---------------------------------------------------------------------------
__global__ void conv_silu_kernel(const float* __restrict__ h,
                                 const float* __restrict__ cw,
                                 const float* __restrict__ cb,
                                 bf16* __restrict__ oh, bf16* __restrict__ ol) {
    int i = blockIdx.x * blockDim.x + threadIdx.x;
    if (i >= MM * DD / 2) return;
    const int D2 = DD / 2;
    int row = i / D2;
    int e   = (i - row * D2) * 2;
    int l   = row % LL;
    float2 cur  = reinterpret_cast<const float2*>(h)[i];
    float2 prev = (l > 0)      ? reinterpret_cast<const float2*>(h)[i - D2] : make_float2(0.f, 0.f);
    float2 next = (l < LL - 1) ? reinterpret_cast<const float2*>(h)[i + D2] : make_float2(0.f, 0.f);
    float v0 = prev.x * __ldg(&cw[e * 3 + 0]) + cur.x * __ldg(&cw[e * 3 + 1])
             + next.x * __ldg(&cw[e * 3 + 2]) + __ldg(&cb[e]);
    float v1 = prev.y * __ldg(&cw[e * 3 + 3]) + cur.y * __ldg(&cw[e * 3 + 4])
             + next.y * __ldg(&cw[e * 3 + 5]) + __ldg(&cb[e + 1]);
    v0 = siluf(v0);
    v1 = siluf(v1);
    uint32_t hh, ll2;
    split2(v0, v1, hh, ll2);
    size_t o = ((size_t)row * KC + DH + e) >> 1;
    reinterpret_cast<uint32_t*>(oh)[o] = hh;
    reinterpret_cast<uint32_t*>(ol)[o] = ll2;
}

// ---------------------------------------------------------------------------
// Chunked scan with on-the-fly A_bar
// ---------------------------------------------------------------------------
__device__ __forceinline__ float abar_of(float xdin, float a) {
    float xd = fmaxf(xdin, 0.0f) + log1pf(expf(-fabsf(xdin)));
    return expf(-xd * a);
}

__global__ void scan1_kernel(const float* __restrict__ dab,
                             float* __restrict__ cp, float* __restrict__ cs) {
    int gid = blockIdx.x * blockDim.x + threadIdx.x;
    if (gid >= BB * NCH * DH) return;
    int h  = gid % DH;
    int ch = (gid / DH) % NCH;
    int b  = gid / (DH * NCH);
    float p = 1.0f, s = 0.0f;
    for (int t = 0; t < CHL; t++) {
        size_t base = ((size_t)(b * LL + ch * CHL + t)) * N3;
        float a  = abar_of(dab[base + h], dab[base + DH + h]);
        float bx = dab[base + 2 * DH + h];
        p *= a;
        s = fmaf(bx, p, s);
    }
    cp[gid] = p;
    cs[gid] = s;
}

__global__ void scan2_kernel(float* __restrict__ cp, float* __restrict__ cs) {
    int gid = blockIdx.x * blockDim.x + threadIdx.x;
    if (gid >= BB * DH) return;
    int b = gid / DH;
    int h = gid - b * DH;
    float P = 1.0f, S = 0.0f;
    for (int ch = 0; ch < NCH; ch++) {
        size_t idx = ((size_t)b * NCH + ch) * DH + h;
        float p = cp[idx], s = cs[idx];
        cp[idx] = P;
        cs[idx] = S;
        S = fmaf(P, s, S);
        P *= p;
    }
}

__global__ void scan3_kernel(const float* __restrict__ dab,
                             const float* __restrict__ cp, const float* __restrict__ cs,
                             bf16* __restrict__ hh, bf16* __restrict__ hl) {
    int gid = blockIdx.x * blockDim.x + threadIdx.x;
    if (gid >= BB * NCH * DH) return;
    int h  = gid % DH;
    int ch = (gid / DH) % NCH;
    int b  = gid / (DH * NCH);
    float p = cp[gid];
    float s = cs[gid];
    for (int t = 0; t < CHL; t++) {
        size_t row  = (size_t)(b * LL + ch * CHL + t);
        size_t base = row * N3;
        float a  = abar_of(dab[base + h], dab[base + DH + h]);
        float bx = dab[base + 2 * DH + h];
        p *= a;
        s = fmaf(bx, p, s);
        size_t o = row * KC + h;
        bf16 hv = __float2bfloat16_rn(s);
        hh[o] = hv;
        hl[o] = __float2bfloat16_rn(s - __bfloat162float(hv));
    }
}

// ---------------------------------------------------------------------------
// LayerNorm -> xn planes
// ---------------------------------------------------------------------------
__global__ __launch_bounds__(256)
void ln_kernel(const float* __restrict__ x, const float* __restrict__ gw,
               const float* __restrict__ bw, bf16* __restrict__ yh,
               bf16* __restrict__ yl) {
    int row = blockIdx.x;
    const float* xr = x + (size_t)row * DD;
    int tid = threadIdx.x;

    __shared__ float red[8];
    __shared__ float stat[2];

    float v[3];
    float sum = 0.0f;
    #pragma unroll
    for (int i = 0; i < 3; i++) { v[i] = xr[tid + i * 256]; sum += v[i]; }
    #pragma unroll
    for (int o = 16; o > 0; o >>= 1) sum += __shfl_xor_sync(0xffffffffu, sum, o);
    if ((tid & 31) == 0) red[tid >> 5] = sum;
    __syncthreads();
    if (tid == 0) {
        float t = 0.0f;
        #pragma unroll
        for (int w = 0; w < 8; w++) t += red[w];
        stat[0] = t;
    }
    __syncthreads();
    float mu = stat[0] * (1.0f / (float)DD);

    float vs = 0.0f;
    #pragma unroll
    for (int i = 0; i < 3; i++) { float d = v[i] - mu; vs += d * d; }
    #pragma unroll
    for (int o = 16; o > 0; o >>= 1) vs += __shfl_xor_sync(0xffffffffu, vs, o);
    if ((tid & 31) == 0) red[tid >> 5] = vs;
    __syncthreads();
    if (tid == 0) {
        float t = 0.0f;
        #pragma unroll
        for (int w = 0; w < 8; w++) t += red[w];
        stat[1] = t;
    }
    __syncthreads();
    float rstd = rsqrtf(stat[1] * (1.0f / (float)DD) + 1e-5f);

    #pragma unroll
    for (int i = 0; i < 3; i++) {
        int e = tid + i * 256;
        float r = (v[i] - mu) * rstd * __ldg(&gw[e]) + __ldg(&bw[e]);
        size_t idx = (size_t)row * DD + e;
        bf16 hv = __float2bfloat16_rn(r);
        yh[idx] = hv;
        yl[idx] = __float2bfloat16_rn(r - __bfloat162float(hv));
    }
}

// ---------------------------------------------------------------------------
// Launcher
// ---------------------------------------------------------------------------
extern "C" void kernel_launch(void* const* d_in, const int* in_sizes, int n_in,
                              void* d_out, int out_size) {
    const int*   tokens  = (const int*)  d_in[0];
    const float* embed   = (const float*)d_in[1];
    const float* lin1_w  = (const float*)d_in[2];
    const float* conv_w  = (const float*)d_in[3];
    const float* conv_b  = (const float*)d_in[4];
    const float* A_w     = (const float*)d_in[5];
    const float* A_b     = (const float*)d_in[6];
    const float* B_w     = (const float*)d_in[7];
    const float* B_b     = (const float*)d_in[8];
    const float* del_w   = (const float*)d_in[9];
    const float* del_b   = (const float*)d_in[10];
    const float* C_w     = (const float*)d_in[11];
    const float* C_b     = (const float*)d_in[12];
    const float* D_w     = (const float*)d_in[13];
    const float* D_b     = (const float*)d_in[14];
    const float* lin2_w  = (const float*)d_in[15];
    const float* last_w  = (const float*)d_in[16];
    const float* ln_g    = (const float*)d_in[17];
    const float* ln_b    = (const float*)d_in[18];
    float* out = (float*)d_out;

    float *x, *h1, *s, *dab, *b3, *bcd, *cp, *cs;
    cudaGetSymbolAddress((void**)&x,   g_x);
    cudaGetSymbolAddress((void**)&h1,  g_h1);
    cudaGetSymbolAddress((void**)&s,   g_s);
    cudaGetSymbolAddress((void**)&dab, g_dab);
    cudaGetSymbolAddress((void**)&b3,  g_b3);
    cudaGetSymbolAddress((void**)&bcd, g_bcd);
    cudaGetSymbolAddress((void**)&cp,  g_cp);
    cudaGetSymbolAddress((void**)&cs,  g_cs);

    bf16 *xh, *xl, *csh, *csl, *sh, *sl, *ggh, *ggl, *xnh, *xnl;
    cudaGetSymbolAddress((void**)&xh,  x_h);  cudaGetSymbolAddress((void**)&xl,  x_l);
    cudaGetSymbolAddress((void**)&csh, cs_h); cudaGetSymbolAddress((void**)&csl, cs_l);
    cudaGetSymbolAddress((void**)&sh,  s_h);  cudaGetSymbolAddress((void**)&sl,  s_l);
    cudaGetSymbolAddress((void**)&ggh, gg_h); cudaGetSymbolAddress((void**)&ggl, gg_l);
    cudaGetSymbolAddress((void**)&xnh, xn_h); cudaGetSymbolAddress((void**)&xnl, xn_l);

    bf16 *p1h, *p1l, *pPh, *pPl, *pcdh, *pcdl, *p2h, *p2l, *pLh, *pLl, *peh, *pel;
    cudaGetSymbolAddress((void**)&p1h, w1_h);   cudaGetSymbolAddress((void**)&p1l, w1_l);
    cudaGetSymbolAddress((void**)&pPh, wP_h);   cudaGetSymbolAddress((void**)&pPl, wP_l);
    cudaGetSymbolAddress((void**)&pcdh, wcd_h); cudaGetSymbolAddress((void**)&pcdl, wcd_l);
    cudaGetSymbolAddress((void**)&p2h, w2_h);   cudaGetSymbolAddress((void**)&p2l, w2_l);
    cudaGetSymbolAddress((void**)&pLh, wL_h);   cudaGetSymbolAddress((void**)&pLl, wL_l);
    cudaGetSymbolAddress((void**)&peh, we_h);   cudaGetSymbolAddress((void**)&pel, we_l);

    const int GS64  = 2 * (2 * 64 * RPITCH + 2 * 64 * RPITCH);     // 40960 (shape1)
    const int GS128 = 2 * (2 * 128 * RPITCH + 2 * 128 * RPITCH);   // 81920 (shape0)
    cudaFuncSetAttribute((void*)gemm_bf3<0,false,0>, cudaFuncAttributeMaxDynamicSharedMemorySize, GS128);
    cudaFuncSetAttribute((void*)gemm_bf3<0,false,1>, cudaFuncAttributeMaxDynamicSharedMemorySize, GS64);
    cudaFuncSetAttribute((void*)gemm_bf3<0,true ,1>, cudaFuncAttributeMaxDynamicSharedMemorySize, GS64);
    cudaFuncSetAttribute((void*)gemm_bf3<2,true ,1>, cudaFuncAttributeMaxDynamicSharedMemorySize, GS64);
    cudaFuncSetAttribute((void*)gemm_bf3<3,true ,1>, cudaFuncAttributeMaxDynamicSharedMemorySize, GS64);

    const dim3 blk128(128), blk256(256);
    const dim3 gd64(DD / 64, MM / 64);               // 12 x 64 = 768 CTAs (shape1)
    const dim3 gdP(N3 / 128, MM / 128);              // 36 x 32 (shape0)
    const dim3 gdV((VV + 127) / 128, MM / 128);      // 393 x 32 (shape0)

    const int ndd = NLAY * DD * DD / 4, nem = VV * DD / 4;
    const int npP = NLAY * 3 * DH * DD / 4, npcd = NLAY * DD * KC / 4;

    // Launch order keeps layer-0 lin1 GEMM at my launch #4 (the profiled slot).
    split_kernel<<<(ndd + 255) / 256, 256>>>(lin1_w, p1h, p1l, ndd);                 // 1
    embed_kernel<<<(MM * (DD / 4) + 255) / 256, 256>>>(tokens, embed, x, xh, xl);    // 2
    bias3_kernel<<<(NLAY * N3 + 255) / 256, 256>>>(del_b, A_b, B_b, b3);             // 3

    for (int i = 0; i < NLAY; i++) {
        size_t odd = (size_t)i * DD * DD;
        size_t opr = (size_t)i * 3 * DH * DD;
        size_t ocd = (size_t)i * DD * KC;
        const float* cw  = conv_w + (size_t)i * DD * 3;
        const float* cb  = conv_b + (size_t)i * DD;

        // h1 = x @ lin1^T  (layer 0: launch #4 -> profiled)
        gemm_bf3<0,false,1><<<gd64, blk128, GS64>>>(xh, xl, p1h + odd, p1l + odd,
            nullptr, nullptr, h1, nullptr, nullptr, MM, DD, DD, DD);

        if (i == 0) {   // remaining prologue, after the profiled GEMM
            biascd_kernel<<<(NLAY * DD + 255) / 256, 256>>>(C_b, D_b, bcd);
            splitP_kernel<<<(npP + 255) / 256, 256>>>(del_w, A_w, B_w, pPh, pPl);
            splitcd_kernel<<<(npcd + 255) / 256, 256>>>(C_w, D_w, pcdh, pcdl);
            split_kernel<<<(ndd + 255) / 256, 256>>>(lin2_w, p2h, p2l, ndd);
            split_kernel<<<(ndd + 255) / 256, 256>>>(last_w, pLh, pLl, ndd);
            split_kernel<<<(nem + 255) / 256, 256>>>(embed,  peh, pel, nem);
        }

        // h2 planes = silu(conv1d(h1)) -> csA[:, DH:]
        conv_silu_kernel<<<(MM * DD / 2 + 255) / 256, 256>>>(h1, cw, cb, csh, csl);
        // fused delta|A|B projection
        gemm_bf3<0,false,0><<<gdP, blk256, GS128>>>(csh + DH, csl + DH, pPh + opr, pPl + opr,
            b3 + (size_t)i * N3, nullptr, dab, nullptr, nullptr, MM, N3, DD, KC);
        // chunked scan -> hs planes into csA[:, :DH]
        scan1_kernel<<<(BB * NCH * DH + 255) / 256, 256>>>(dab, cp, cs);
        scan2_kernel<<<(BB * DH + 255) / 256, 256>>>(cp, cs);
        scan3_kernel<<<(BB * NCH * DH + 255) / 256, 256>>>(dab, cp, cs, csh, csl);
        // s = [hs|h2] @ [Cw|Dw]^T + (Cb+Db)
        gemm_bf3<0,true,1><<<gd64, blk128, GS64>>>(csh, csl, pcdh + ocd, pcdl + ocd,
            bcd + (size_t)i * DD, nullptr, s, sh, sl, MM, DD, KC, KC);
        // gate = s * silu(s @ lin2^T)
        gemm_bf3<3,true,1><<<gd64, blk128, GS64>>>(sh, sl, p2h + odd, p2l + odd,
            nullptr, s, nullptr, ggh, ggl, MM, DD, DD, DD);
        // x = s + gate @ last^T
        gemm_bf3<2,true,1><<<gd64, blk128, GS64>>>(ggh, ggl, pLh + odd, pLl + odd,
            nullptr, s, x, xh, xl, MM, DD, DD, DD);
    }

    ln_kernel<<<MM, 256>>>(x, ln_g, ln_b, xnh, xnl);
    gemm_bf3<0,false,0><<<gdV, blk256, GS128>>>(xnh, xnl, peh, pel,
        nullptr, nullptr, out, nullptr, nullptr, MM, VV, DD, DD);
}